// round 5
// baseline (speedup 1.0000x reference)
#include <cuda_runtime.h>

// GCN 2-layer: x[50000,64] f32, edge_index[2,800000] int32 (JAX x64 disabled),
// W1[64,64], b1[64], W2[64,16], b2[16] -> log_softmax out[50000,16] f32.
//
// out1[c] = dinv[c] * ( sum_{e: col=c} hs1[row_e] + hs1[c] ) + b1   (hs1 = (x@W1)*dinv)
// relu, then same structure for layer 2, then log_softmax.

#define NMAX 50048   // 50000 rounded up to 64

__device__ __align__(16) float g_dinv[NMAX];
__device__ __align__(16) int   g_deg [NMAX];
__device__ __align__(16) float g_hs1 [NMAX * 64];
__device__ __align__(16) float g_acc1[NMAX * 64];
__device__ __align__(16) float g_hs2 [NMAX * 16];
__device__ __align__(16) float g_acc2[NMAX * 16];

// Vector global reduction with explicit generic->global conversion.
__device__ __forceinline__ void red_add_v4(float* dst, float4 v) {
    asm volatile("red.global.add.v4.f32 [%0], {%1,%2,%3,%4};"
                 :: "l"(__cvta_generic_to_global(dst)),
                    "f"(v.x), "f"(v.y), "f"(v.z), "f"(v.w)
                 : "memory");
}

// ---------------------------------------------------------------- degree ----
__global__ void k_deg_init(int N) {
    int i = blockIdx.x * 256 + threadIdx.x;
    if (i < N) g_deg[i] = 1;                       // self-loop
}

__global__ void k_deg_count(const int* __restrict__ col, int E) {
    int e = blockIdx.x * 256 + threadIdx.x;
    if (e < E) atomicAdd(&g_deg[col[e]], 1);
}

// dinv = rsqrt(deg); also zero both accumulators. Grid covers N*16 threads.
__global__ void k_dinv_zero(int N) {
    int i = blockIdx.x * 256 + threadIdx.x;
    if (i < N) g_dinv[i] = rsqrtf((float)g_deg[i]);
    float4 z = make_float4(0.f, 0.f, 0.f, 0.f);
    if (i < N * 16) ((float4*)g_acc1)[i] = z;      // N*64 floats = N*16 float4
    if (i < N * 4)  ((float4*)g_acc2)[i] = z;      // N*16 floats
}

// ------------------------------------------------------- GEMM1 + prescale ----
// hs1[n][f] = (x[n,:] @ W1[:,f]) * dinv[n].  Block: 64 nodes x 64 f,
// 256 threads, 4x4 register tile per thread.
__global__ void k_gemm1(const float* __restrict__ x, const float* __restrict__ W,
                        int N) {
    __shared__ float xs[64 * 65];   // xs[n*65+k], padded
    __shared__ float ws[64 * 64];   // ws[k*64+f]
    int t = threadIdx.x;
    int nbase = blockIdx.x * 64;

#pragma unroll
    for (int i = 0; i < 16; i++) ws[t + i * 256] = W[t + i * 256];
#pragma unroll
    for (int i = 0; i < 16; i++) {
        int idx = t + i * 256;                 // 0..4095 over 64 nodes x 64 k
        int nl = idx >> 6, k = idx & 63;
        int n = nbase + nl;
        xs[nl * 65 + k] = (n < N) ? x[n * 64 + k] : 0.f;
    }
    __syncthreads();

    int r = t >> 4;        // node group: nodes 4r..4r+3
    int c = t & 15;        // f group: f = 4c..4c+3
    float acc[4][4];
#pragma unroll
    for (int i = 0; i < 4; i++)
#pragma unroll
        for (int j = 0; j < 4; j++) acc[i][j] = 0.f;

#pragma unroll
    for (int k = 0; k < 64; k++) {
        float xv[4];
#pragma unroll
        for (int i = 0; i < 4; i++) xv[i] = xs[(4 * r + i) * 65 + k];
        float4 wv = *(const float4*)&ws[k * 64 + 4 * c];
#pragma unroll
        for (int i = 0; i < 4; i++) {
            acc[i][0] += xv[i] * wv.x;
            acc[i][1] += xv[i] * wv.y;
            acc[i][2] += xv[i] * wv.z;
            acc[i][3] += xv[i] * wv.w;
        }
    }
#pragma unroll
    for (int i = 0; i < 4; i++) {
        int n = nbase + 4 * r + i;
        if (n < N) {
            float d = g_dinv[n];
            float4 o = make_float4(acc[i][0] * d, acc[i][1] * d,
                                   acc[i][2] * d, acc[i][3] * d);
            *(float4*)&g_hs1[n * 64 + 4 * c] = o;
        }
    }
}

// ------------------------------------------------------------- scatter 1 ----
// thread i: edge e = i>>4, float4 chunk (i&15). acc1[col] += hs1[row] (vec RED).
__global__ void k_scatter1(const int* __restrict__ row,
                           const int* __restrict__ col, int E) {
    int i = blockIdx.x * 256 + threadIdx.x;
    int e = i >> 4;
    if (e >= E) return;
    int c4 = (i & 15) << 2;
    int r = row[e];
    int c = col[e];
    float4 v = *(const float4*)&g_hs1[r * 64 + c4];
    red_add_v4(&g_acc1[c * 64 + c4], v);
}

// -------------------------------------- finalize1 + GEMM2 + prescale fused ----
// tmp[n][f] = relu(dinv[n]*(acc1+hs1)[n][f] + b1[f])
// hs2[n][j] = (tmp[n,:] @ W2[:,j]) * dinv[n]
__global__ void k_fin1_gemm2(const float* __restrict__ b1,
                             const float* __restrict__ W2, int N) {
    __shared__ float ts[64 * 65];    // ts[k*65 + nloc] (transposed, padded)
    __shared__ float ws[64 * 16];    // W2[k*16+j]
    int t = threadIdx.x;
    int nbase = blockIdx.x * 64;

    ws[t] = W2[t]; ws[t + 256] = W2[t + 256];
    ws[t + 512] = W2[t + 512]; ws[t + 768] = W2[t + 768];

#pragma unroll
    for (int i = 0; i < 16; i++) {
        int idx = t + i * 256;                 // 64 nodes x 64 f
        int nl = idx >> 6, f = idx & 63;
        int n = nbase + nl;
        float v = 0.f;
        if (n < N) {
            v = g_dinv[n] * (g_acc1[n * 64 + f] + g_hs1[n * 64 + f]) + b1[f];
            v = fmaxf(v, 0.f);
        }
        ts[f * 65 + nl] = v;
    }
    __syncthreads();

    int nl = t >> 2;          // local node 0..63
    int fq = (t & 3) << 2;    // output features fq..fq+3
    float4 a = make_float4(0.f, 0.f, 0.f, 0.f);
#pragma unroll
    for (int k = 0; k < 64; k++) {
        float xk = ts[k * 65 + nl];
        float4 wv = *(const float4*)&ws[k * 16 + fq];
        a.x += xk * wv.x; a.y += xk * wv.y;
        a.z += xk * wv.z; a.w += xk * wv.w;
    }
    int n = nbase + nl;
    if (n < N) {
        float d = g_dinv[n];
        a.x *= d; a.y *= d; a.z *= d; a.w *= d;
        *(float4*)&g_hs2[n * 16 + fq] = a;
    }
}

// ------------------------------------------------------------- scatter 2 ----
__global__ void k_scatter2(const int* __restrict__ row,
                           const int* __restrict__ col, int E) {
    int i = blockIdx.x * 256 + threadIdx.x;
    int e = i >> 2;
    if (e >= E) return;
    int c4 = (i & 3) << 2;
    int r = row[e];
    int c = col[e];
    float4 v = *(const float4*)&g_hs2[r * 16 + c4];
    red_add_v4(&g_acc2[c * 16 + c4], v);
}

// ---------------------------------------------- finalize2 + log_softmax ----
// 16 lanes per node; shfl_xor reductions stay inside aligned 16-lane groups.
__global__ void k_final(const float* __restrict__ b2, float* __restrict__ out,
                        int N) {
    int i = blockIdx.x * 256 + threadIdx.x;
    int n = i >> 4;
    int j = i & 15;
    if (n >= N) return;
    float v = g_dinv[n] * (g_acc2[n * 16 + j] + g_hs2[n * 16 + j]) + b2[j];

    float m = v;
#pragma unroll
    for (int off = 8; off >= 1; off >>= 1)
        m = fmaxf(m, __shfl_xor_sync(0xffffffffu, m, off));
    float ex = __expf(v - m);
    float s = ex;
#pragma unroll
    for (int off = 8; off >= 1; off >>= 1)
        s += __shfl_xor_sync(0xffffffffu, s, off);
    out[n * 16 + j] = v - m - __logf(s);
}

// ------------------------------------------------------------------ host ----
extern "C" void kernel_launch(void* const* d_in, const int* in_sizes, int n_in,
                              void* d_out, int out_size) {
    const float* x  = (const float*)d_in[0];
    const int*   ei = (const int*)d_in[1];      // int32: JAX x64 disabled
    const float* W1 = (const float*)d_in[2];
    const float* b1 = (const float*)d_in[3];
    const float* W2 = (const float*)d_in[4];
    const float* b2 = (const float*)d_in[5];
    float*       out = (float*)d_out;

    int N = in_sizes[0] / 64;
    int E = in_sizes[1] / 2;
    const int* row = ei;        // sources
    const int* col = ei + E;    // targets

    int gN   = (N + 255) / 256;
    int gE   = (E + 255) / 256;
    int gN16 = (N * 16 + 255) / 256;
    int gT   = (N + 63) / 64;         // 64-node tiles
    int gS1  = (E * 16 + 255) / 256;  // 16 chunks/edge
    int gS2  = (E * 4 + 255) / 256;   // 4 chunks/edge

    k_deg_init  <<<gN,   256>>>(N);
    k_deg_count <<<gE,   256>>>(col, E);
    k_dinv_zero <<<gN16, 256>>>(N);
    k_gemm1     <<<gT,   256>>>(x, W1, N);
    k_scatter1  <<<gS1,  256>>>(row, col, E);
    k_fin1_gemm2<<<gT,   256>>>(b1, W2, N);
    k_scatter2  <<<gS2,  256>>>(row, col, E);
    k_final     <<<gN16, 256>>>(b2, out, N);
}